// round 13
// baseline (speedup 1.0000x reference)
#include <cuda_runtime.h>
#include <cstdint>

#define NPTS   16384
#define NBINS  256
#define CAP    512                 // padded slots per bin (center mean ~306, +12 sigma)
#define ZMIN   (-6.0f)
#define DZ     (12.0f / 256.0f)
#define INV_DZ (256.0f / 12.0f)
#define GRID   128
#define TPB    512                 // 16 warps/CTA -> 2048 warps
#define NWARPS (GRID * (TPB / 32))
#define NGROUPS (2 * NBINS * 16)   // dir x bin x chunk-slot (CAP/32 = 16)

// Zero-initialized at load; finalizer resets what must be zero per replay.
// Barrier state (g_arrive, g_flag) is monotonic -> replay-safe, never reset.
__device__ int      g_cursor[2][NBINS];
__device__ float4   g_bins[2][NBINS * CAP];  // (-2x,-2y,-2z,|p|^2)
__device__ float    g_sum;
__device__ unsigned g_done;
__device__ unsigned g_arrive;
__device__ unsigned g_flag[GRID];

__device__ __forceinline__ int zbin(float z) {
    int b = (int)floorf((z - ZMIN) * INV_DZ);
    return max(0, min(NBINS - 1, b));
}

// ---- L2-coherent primitives ------------------------------------------------
__device__ __forceinline__ unsigned ld_acq(unsigned* p) {
    unsigned v;
    asm volatile("ld.acquire.gpu.global.u32 %0, [%1];" : "=r"(v) : "l"(p) : "memory");
    return v;
}
__device__ __forceinline__ void st_rel(unsigned* p, unsigned v) {
    asm volatile("st.release.gpu.global.u32 [%0], %1;" :: "l"(p), "r"(v) : "memory");
}
__device__ __forceinline__ unsigned atom_add_acqrel(unsigned* p, unsigned v) {
    unsigned o;
    asm volatile("atom.add.acq_rel.gpu.global.u32 %0, [%1], %2;"
                 : "=r"(o) : "l"(p), "r"(v) : "memory");
    return o;
}

// Grid barrier v3: parallel distributed release (R10-proven).
// GRID=128 <= 148 SMs -> all CTAs co-resident in wave 1.
__device__ __forceinline__ void grid_barrier() {
    __shared__ unsigned sh_gen;
    __shared__ int      sh_last;
    __syncthreads();
    if (threadIdx.x == 0) {
        unsigned my = ld_acq(&g_flag[blockIdx.x]);
        sh_gen = my;
        __threadfence();
        unsigned old = atom_add_acqrel(&g_arrive, 1u);
        sh_last = ((old + 1u) % GRID == 0u);
    }
    __syncthreads();
    if (sh_last) {
        if (threadIdx.x < GRID)
            st_rel(&g_flag[threadIdx.x], sh_gen + 1u);   // 128 stores in parallel
    } else if (threadIdx.x == 0) {
        unsigned gen = sh_gen;
        while (ld_acq(&g_flag[blockIdx.x]) == gen) __nanosleep(64);
    }
    __syncthreads();
}

// Broadcast-candidate bin scan: every lane loads the SAME candidate (1
// wavefront) and tests it against its OWN source point.
__device__ __forceinline__ void scan_bin_bcast(const float4* __restrict__ T,
                                               int base, int n,
                                               float sx, float sy, float sz,
                                               float& m) {
#pragma unroll 4
    for (int j = 0; j < n; j++) {
        float4 t = T[base + j];
        float d = fmaf(sx, t.x, t.w);
        d = fmaf(sy, t.y, d);
        d = fmaf(sz, t.z, d);
        m = fminf(m, d);
    }
}

__global__ void __launch_bounds__(TPB, 1) chamfer_fused(
    const float* __restrict__ pred, const float* __restrict__ tgt,
    float* __restrict__ out)
{
    __shared__ int   sh_cnt[2 * NBINS];
    __shared__ float red[TPB];

    const int tid  = threadIdx.x;
    const int lane = tid & 31;

    // ---- Phase A: scatter into padded z-bins (coalesced reads) -------------
    {
        const int gidx = blockIdx.x * TPB + tid;    // 0..65535; half do work
        if (gidx < 2 * NPTS) {
            const int pdir = gidx >> 14;
            const int pi   = gidx & (NPTS - 1);
            const float* __restrict__ P = pdir ? tgt : pred;
            const float px = P[3 * pi + 0];
            const float py = P[3 * pi + 1];
            const float pz = P[3 * pi + 2];
            const int  b = zbin(pz);
            const int slot = atomicAdd(&g_cursor[pdir][b], 1);
            if (slot < CAP)
                g_bins[pdir][(b << 9) + slot] =
                    make_float4(-2.0f * px, -2.0f * py, -2.0f * pz,
                                px * px + py * py + pz * pz);
        }
    }

    grid_barrier();    // the ONLY device-wide sync

    if (tid < 2 * NBINS) sh_cnt[tid] = min(((int*)g_cursor)[tid], CAP);
    __syncthreads();

    // ---- Phase B: NN — one source point per LANE, candidates broadcast -----
    const int wid = blockIdx.x * (TPB / 32) + (tid >> 5);   // 0..2047
    float acc = 0.0f;

    for (int grp = wid; grp < NGROUPS; grp += NWARPS) {
        const int dir   = grp >> 12;           // warp-uniform
        const int rem   = grp & 4095;
        const int chunk = rem >> 8;            // bin-major: heavy bins spread over CTAs
        const int bin   = rem & 255;

        const int cnt_s = sh_cnt[dir * NBINS + bin];
        const int s0    = chunk * 32;
        if (s0 >= cnt_s) continue;             // empty chunk: skip (warp-uniform)

        const bool valid = (s0 + lane) < cnt_s;
        // Safe to read even if invalid (slot < CAP always inside the bin pad).
        float4 a = g_bins[dir][(bin << 9) + s0 + lane];
        const float sx = -0.5f * a.x;
        const float sy = -0.5f * a.y;
        const float sz = -0.5f * a.z;
        const float sn = valid ? a.w : 0.0f;
        const float zs = sz;

        const int tdir = dir ^ 1;
        const float4* __restrict__ T = g_bins[tdir];
        const int* cnt = &sh_cnt[tdir * NBINS];

        float m = valid ? 3.4e38f : -3.4e38f;  // invalid lanes: need==false forever
        scan_bin_bcast(T, bin << 9, cnt[bin], sx, sy, sz, m);
        int lo = bin, hi = bin + 1;

        while (true) {
            float dlo = (lo > 0)     ? (zs - (ZMIN + (float)lo * DZ)) : 1e30f;
            float dhi = (hi < NBINS) ? ((ZMIN + (float)hi * DZ) - zs) : 1e30f;
            float g = fminf(dlo, dhi);
            bool need = valid && (sn + m > g * g);   // g=1e30 -> inf -> false
            if (!__any_sync(0xFFFFFFFFu, need)) break;
            int b;
            if (dlo < dhi) { lo--; b = lo; }         // dlo/dhi warp-uniform enough:
            else           { b = hi; hi++; }         // lanes share a bin => same edges
            scan_bin_bcast(T, b << 9, cnt[b], sx, sy, sz, m);
        }
        if (valid) acc += sn + m;               // = min_j ||s - t_j||^2
    }

    // ---- Phase C: reduce + last-block finalize -----------------------------
    red[tid] = acc;
    __syncthreads();
    for (int s = TPB / 2; s > 0; s >>= 1) {
        if (tid < s) red[tid] += red[tid + s];
        __syncthreads();
    }
    if (tid == 0) {
        atomicAdd(&g_sum, red[0]);
        if ((atom_add_acqrel(&g_done, 1u) + 1u) % GRID == 0u) {
            float total = atomicExch(&g_sum, 0.0f);
            out[0] = total / (float)(2 * NPTS);   // (mean_pt + mean_tp)/2
            for (int c = 0; c < 2 * NBINS; c++) ((int*)g_cursor)[c] = 0;
        }
    }
}

extern "C" void kernel_launch(void* const* d_in, const int* in_sizes, int n_in,
                              void* d_out, int out_size)
{
    const float* pred = (const float*)d_in[0];
    const float* tgt  = (const float*)d_in[1];
    float* out = (float*)d_out;

    chamfer_fused<<<GRID, TPB>>>(pred, tgt, out);
}

// round 14
// speedup vs baseline: 6.2565x; 6.2565x over previous
#include <cuda_runtime.h>
#include <cstdint>

#define NPTS   16384
#define GY     64
#define GZ     64
#define NCELL  (GY * GZ)            // 4096
#define CAP2   128                  // slots/cell (center mean ~41, >+10 sigma pad)
#define YMIN   (-4.0f)
#define CELL   (8.0f / 64.0f)       // 0.125
#define INV_CELL (64.0f / 8.0f)
#define GRID   128
#define TPB    1024                 // 32 warps/CTA; 4096 warps; 8 points/warp

// Zero-initialized at load; finalizer resets cursors each replay.
// Barrier state (g_arrive, g_flag, g_done) is monotonic -> never reset.
__device__ int      g_cursor[2][NCELL];
__device__ float4   g_cells[2][NCELL * CAP2];   // (-2x,-2y,-2z,|p|^2)
__device__ float    g_sum;
__device__ unsigned g_done;
__device__ unsigned g_arrive;
__device__ unsigned g_flag[GRID];

__device__ __forceinline__ int clampi(int v, int lo, int hi) {
    return max(lo, min(hi, v));
}
__device__ __forceinline__ int cell_coord(float v) {
    return clampi((int)floorf((v - YMIN) * INV_CELL), 0, GY - 1);
}

// ---- L2-coherent primitives ------------------------------------------------
__device__ __forceinline__ unsigned ld_acq(unsigned* p) {
    unsigned v;
    asm volatile("ld.acquire.gpu.global.u32 %0, [%1];" : "=r"(v) : "l"(p) : "memory");
    return v;
}
__device__ __forceinline__ void st_rel(unsigned* p, unsigned v) {
    asm volatile("st.release.gpu.global.u32 [%0], %1;" :: "l"(p), "r"(v) : "memory");
}
__device__ __forceinline__ unsigned atom_add_acqrel(unsigned* p, unsigned v) {
    unsigned o;
    asm volatile("atom.add.acq_rel.gpu.global.u32 %0, [%1], %2;"
                 : "=r"(o) : "l"(p), "r"(v) : "memory");
    return o;
}

// Grid barrier v3: parallel distributed release (R10-proven).
// GRID=128 <= 148 SMs -> all CTAs co-resident in wave 1.
__device__ __forceinline__ void grid_barrier() {
    __shared__ unsigned sh_gen;
    __shared__ int      sh_lastb;
    __syncthreads();
    if (threadIdx.x == 0) {
        unsigned my = ld_acq(&g_flag[blockIdx.x]);
        sh_gen = my;
        __threadfence();
        unsigned old = atom_add_acqrel(&g_arrive, 1u);
        sh_lastb = ((old + 1u) % GRID == 0u);
    }
    __syncthreads();
    if (sh_lastb) {
        if (threadIdx.x < GRID)
            st_rel(&g_flag[threadIdx.x], sh_gen + 1u);   // 128 stores in parallel
    } else if (threadIdx.x == 0) {
        unsigned gen = sh_gen;
        while (ld_acq(&g_flag[blockIdx.x]) == gen) __nanosleep(64);
    }
    __syncthreads();
}

__device__ __forceinline__ float warp_min(float v) {
    v = fminf(v, __shfl_xor_sync(0xFFFFFFFFu, v, 16));
    v = fminf(v, __shfl_xor_sync(0xFFFFFFFFu, v, 8));
    v = fminf(v, __shfl_xor_sync(0xFFFFFFFFu, v, 4));
    v = fminf(v, __shfl_xor_sync(0xFFFFFFFFu, v, 2));
    v = fminf(v, __shfl_xor_sync(0xFFFFFFFFu, v, 1));
    return v;
}

// Warp-cooperative cell scan: lanes stride this cell's candidates (coalesced).
__device__ __forceinline__ void scan_cell(const float4* __restrict__ T,
                                          const int* __restrict__ cnt,
                                          int cell, int lane,
                                          float sx, float sy, float sz,
                                          float& m) {
    const int n    = cnt[cell];
    const int base = cell << 7;            // CAP2 = 128
    float ma = 3.4e38f, mb = 3.4e38f;
    int j = lane;
    for (; j + 32 < n; j += 64) {
        float4 ta = T[base + j];
        float4 tb = T[base + j + 32];
        float da = fmaf(sx, ta.x, ta.w);
        float db = fmaf(sx, tb.x, tb.w);
        da = fmaf(sy, ta.y, da);
        db = fmaf(sy, tb.y, db);
        da = fmaf(sz, ta.z, da);
        db = fmaf(sz, tb.z, db);
        ma = fminf(ma, da);
        mb = fminf(mb, db);
    }
    if (j < n) {
        float4 ta = T[base + j];
        float da = fmaf(sx, ta.x, ta.w);
        da = fmaf(sy, ta.y, da);
        da = fmaf(sz, ta.z, da);
        ma = fminf(ma, da);
    }
    m = fminf(m, fminf(ma, mb));
}

__global__ void __launch_bounds__(TPB, 1) chamfer_fused(
    const float* __restrict__ pred, const float* __restrict__ tgt,
    float* __restrict__ out)
{
    __shared__ int   sh_cnt[NCELL];      // target-direction cell counts (16KB)
    __shared__ float red[TPB];
    __shared__ int   sh_last;

    const int tid  = threadIdx.x;
    const int lane = tid & 31;

    // ---- Phase A: scatter into padded (y,z) cells --------------------------
    {
        const int gidx = blockIdx.x * 256 + (tid & 255);   // 0..32767
        if (tid < 256) {
            const int pdir = gidx >> 14;
            const int pi   = gidx & (NPTS - 1);
            const float* __restrict__ P = pdir ? tgt : pred;
            const float px = P[3 * pi + 0];
            const float py = P[3 * pi + 1];
            const float pz = P[3 * pi + 2];
            const int cell = cell_coord(py) * GZ + cell_coord(pz);
            const int slot = atomicAdd(&g_cursor[pdir][cell], 1);
            if (slot < CAP2)
                g_cells[pdir][(cell << 7) + slot] =
                    make_float4(-2.0f * px, -2.0f * py, -2.0f * pz,
                                px * px + py * py + pz * pz);
        }
    }

    grid_barrier();    // the ONLY device-wide sync

    // ---- target-direction counts into smem ---------------------------------
    // All warps of this CTA process points of ONE direction (256-point span).
    const int gw    = blockIdx.x * (TPB / 32) + (tid >> 5);  // warp 0..4095
    const int pbase = gw * 8;
    const int dir   = pbase >> 14;
    const int tdir  = dir ^ 1;
    for (int c = tid; c < NCELL; c += TPB)
        sh_cnt[c] = min(g_cursor[tdir][c], CAP2);
    __syncthreads();

    const float4* __restrict__ T = g_cells[tdir];
    const float* __restrict__ P = dir ? tgt : pred;

    // ---- Phase B: warp-per-point NN with 2D ring pruning -------------------
    float acc = 0.0f;
#pragma unroll 1
    for (int k = 0; k < 8; k++) {
        const int pi = (pbase + k) & (NPTS - 1);
        const float sx = P[3 * pi + 0];      // broadcast loads
        const float sy = P[3 * pi + 1];
        const float sz = P[3 * pi + 2];
        const float sn = sx * sx + sy * sy + sz * sz;
        const int cy = cell_coord(sy);
        const int cz = cell_coord(sz);

        float m = 3.4e38f;
        scan_cell(T, sh_cnt, cy * GZ + cz, lane, sx, sy, sz, m);
        float wm = warp_min(m);

        int K = 0;
        while (true) {
            // distance from s to the unscanned region outside the K-square;
            // sides at grid edge are infinite (edge cells own all outliers).
            float gyl = (cy - K > 0)      ? sy - (YMIN + (float)(cy - K) * CELL)     : 1e30f;
            float gyh = (cy + K < GY - 1) ? (YMIN + (float)(cy + K + 1) * CELL) - sy : 1e30f;
            float gzl = (cz - K > 0)      ? sz - (YMIN + (float)(cz - K) * CELL)     : 1e30f;
            float gzh = (cz + K < GZ - 1) ? (YMIN + (float)(cz + K + 1) * CELL) - sz : 1e30f;
            float g = fmaxf(0.0f, fminf(fminf(gyl, gyh), fminf(gzl, gzh)));
            if (sn + wm <= g * g) break;     // all-infinite -> inf -> break
            K++;
            const int ylo = cy - K, yhi = cy + K;
            const int zlo = cz - K, zhi = cz + K;
            const int y0 = max(ylo, 0), y1 = min(yhi, GY - 1);
            const int z0 = max(zlo + 1, 0), z1 = min(zhi - 1, GZ - 1);
            if (zlo >= 0)
                for (int iy = y0; iy <= y1; iy++)
                    scan_cell(T, sh_cnt, iy * GZ + zlo, lane, sx, sy, sz, m);
            if (zhi <= GZ - 1)
                for (int iy = y0; iy <= y1; iy++)
                    scan_cell(T, sh_cnt, iy * GZ + zhi, lane, sx, sy, sz, m);
            if (ylo >= 0)
                for (int iz = z0; iz <= z1; iz++)
                    scan_cell(T, sh_cnt, ylo * GZ + iz, lane, sx, sy, sz, m);
            if (yhi <= GY - 1)
                for (int iz = z0; iz <= z1; iz++)
                    scan_cell(T, sh_cnt, yhi * GZ + iz, lane, sx, sy, sz, m);
            wm = warp_min(m);
        }
        if (lane == 0) acc += sn + wm;       // = min_j ||s - t_j||^2
    }

    // ---- Phase C: reduce + last-block finalize (parallel reset) ------------
    red[tid] = acc;
    __syncthreads();
    for (int s = TPB / 2; s > 0; s >>= 1) {
        if (tid < s) red[tid] += red[tid + s];
        __syncthreads();
    }
    if (tid == 0) {
        atomicAdd(&g_sum, red[0]);
        sh_last = ((atom_add_acqrel(&g_done, 1u) + 1u) % GRID == 0u);
    }
    __syncthreads();
    if (sh_last) {
        if (tid == 0) {
            float total = atomicExch(&g_sum, 0.0f);
            out[0] = total / (float)(2 * NPTS);   // (mean_pt + mean_tp)/2
        }
        for (int c = tid; c < 2 * NCELL; c += TPB)
            ((int*)g_cursor)[c] = 0;              // reset for next replay
    }
}

extern "C" void kernel_launch(void* const* d_in, const int* in_sizes, int n_in,
                              void* d_out, int out_size)
{
    const float* pred = (const float*)d_in[0];
    const float* tgt  = (const float*)d_in[1];
    float* out = (float*)d_out;

    chamfer_fused<<<GRID, TPB>>>(pred, tgt, out);
}